// round 2
// baseline (speedup 1.0000x reference)
#include <cuda_runtime.h>

#define BATCH 16
#define CIN   256
#define IMG   64
#define HW    4096
#define NHEADS 8
#define NQ    64
#define NKEY  196
#define NKP   200
#define DQK   32
#define DV    32
#define ATTN_SCALE 0.17677669529663687f

// Scratch (allocation-free rule: __device__ globals)
__device__ float g_q [BATCH * HW * 256];   // [b][h][w][256]  (head*32+d)
__device__ float g_kv[BATCH * HW * 512];   // [b][h][w][512]  (head*64 + d; d<32 = K, d>=32 = V)

__device__ __forceinline__ float f2tf(float x) {
    unsigned r;
    asm("cvt.rna.tf32.f32 %0, %1;" : "=r"(r) : "f"(x));
    return __uint_as_float(r);
}

__device__ __forceinline__ void mma_tf32(float& c0, float& c1, float& c2, float& c3,
                                         unsigned a0, unsigned a1, unsigned a2, unsigned a3,
                                         unsigned b0, unsigned b1) {
    asm volatile(
        "mma.sync.aligned.m16n8k8.row.col.f32.tf32.tf32.f32 "
        "{%0,%1,%2,%3},{%4,%5,%6,%7},{%8,%9},{%0,%1,%2,%3};\n"
        : "+f"(c0), "+f"(c1), "+f"(c2), "+f"(c3)
        : "r"(a0), "r"(a1), "r"(a2), "r"(a3), "r"(b0), "r"(b1));
}

// ---------------------------------------------------------------------------
// Kernel 1: QKV projection GEMM.  C[m][n] = sum_c x[b,c,m] * W[n][c]
// M tile 64 (within one image), N tile 64 (q cols 0..255 -> g_q, 256..767 -> g_kv)
// ---------------------------------------------------------------------------
__global__ __launch_bounds__(128) void qkv_gemm(const float* __restrict__ x,
                                                const float* __restrict__ Wq,
                                                const float* __restrict__ Wkv) {
    __shared__ float As[64 * 20];   // [m][k], stride 20 -> conflict-free frag reads
    __shared__ float Bs[16 * 72];   // [k][n], stride 72 -> conflict-free frag reads

    const int ntile = blockIdx.x;            // 0..11
    const int mtile = blockIdx.y;            // 0..1023
    const int b     = mtile >> 6;
    const int mbase = (mtile & 63) << 6;
    const int nbase = ntile << 6;

    const float* xb = x + (size_t)b * CIN * HW;

    const int tid  = threadIdx.x;
    const int lane = tid & 31, warp = tid >> 5;
    const int wr = warp >> 1, wc = warp & 1;      // 2x2 warps of 32x32
    const int g = lane >> 2, tig = lane & 3;

    float acc[2][4][4];
#pragma unroll
    for (int mt = 0; mt < 2; mt++)
#pragma unroll
        for (int nt = 0; nt < 4; nt++)
#pragma unroll
            for (int j = 0; j < 4; j++) acc[mt][nt][j] = 0.f;

    for (int kt = 0; kt < 16; kt++) {
        const int kc = kt * 16;
        __syncthreads();
        // A tile: 64 m x 16 k (coalesced along m)
#pragma unroll
        for (int i = 0; i < 8; i++) {
            int idx = tid + i * 128;
            int m = idx & 63, kk = idx >> 6;
            As[m * 20 + kk] = f2tf(xb[(size_t)(kc + kk) * HW + mbase + m]);
        }
        // B tile: 16 k x 64 n   (B[k][n] = W[n][k])
#pragma unroll
        for (int i = 0; i < 8; i++) {
            int idx = tid + i * 128;
            int kk = idx & 15, n = idx >> 4;
            int ng = nbase + n;
            const float* Wp = (ng < 256) ? (Wq + (size_t)ng * CIN)
                                         : (Wkv + (size_t)(ng - 256) * CIN);
            Bs[kk * 72 + n] = f2tf(Wp[kc + kk]);
        }
        __syncthreads();

#pragma unroll
        for (int ks = 0; ks < 2; ks++) {
            const int k0 = ks * 8;
            unsigned a[2][4];
#pragma unroll
            for (int mt = 0; mt < 2; mt++) {
                int r = wr * 32 + mt * 16 + g;
                a[mt][0] = __float_as_uint(As[r * 20 + k0 + tig]);
                a[mt][1] = __float_as_uint(As[(r + 8) * 20 + k0 + tig]);
                a[mt][2] = __float_as_uint(As[r * 20 + k0 + tig + 4]);
                a[mt][3] = __float_as_uint(As[(r + 8) * 20 + k0 + tig + 4]);
            }
#pragma unroll
            for (int nt = 0; nt < 4; nt++) {
                int cB = wc * 32 + nt * 8 + g;
                unsigned b0 = __float_as_uint(Bs[(k0 + tig) * 72 + cB]);
                unsigned b1 = __float_as_uint(Bs[(k0 + tig + 4) * 72 + cB]);
#pragma unroll
                for (int mt = 0; mt < 2; mt++)
                    mma_tf32(acc[mt][nt][0], acc[mt][nt][1], acc[mt][nt][2], acc[mt][nt][3],
                             a[mt][0], a[mt][1], a[mt][2], a[mt][3], b0, b1);
            }
        }
    }

    // Epilogue — whole 64-col block lands either in q or kv (boundary 256 % 64 == 0)
    float* dst; int stride, noff;
    if (nbase < 256) { dst = g_q;  stride = 256; noff = nbase; }
    else             { dst = g_kv; stride = 512; noff = nbase - 256; }
    const size_t rowbase = (size_t)b * HW + mbase;

#pragma unroll
    for (int mt = 0; mt < 2; mt++) {
        int r0 = wr * 32 + mt * 16 + g;
#pragma unroll
        for (int nt = 0; nt < 4; nt++) {
            int c = wc * 32 + nt * 8 + 2 * tig;
            float2 v0 = make_float2(acc[mt][nt][0], acc[mt][nt][1]);
            float2 v1 = make_float2(acc[mt][nt][2], acc[mt][nt][3]);
            *(float2*)&dst[(rowbase + r0    ) * stride + noff + c] = v0;
            *(float2*)&dst[(rowbase + r0 + 8) * stride + noff + c] = v1;
        }
    }
}

// ---------------------------------------------------------------------------
// Kernel 2: halo attention. One CTA per (window, batch, head). 4 warps.
// smem: Vs[200][40] | union( Qs[64][36] + Ks[200][36] , Ps[64][212] )
// ---------------------------------------------------------------------------
#define SM_VS    0
#define SM_QS    8000
#define SM_KS    (8000 + 2304)
#define SM_PS    8000
#define SM_FLOATS (8000 + 13568)   // 21568 floats = 86272 bytes

__global__ __launch_bounds__(128) void halo_attn(const float* __restrict__ pb,
                                                 float* __restrict__ out) {
    extern __shared__ float smem[];
    float* Vs = smem + SM_VS;   // [key][d]   stride 40
    float* Qs = smem + SM_QS;   // [q][d]     stride 36
    float* Ks = smem + SM_KS;   // [key][d]   stride 36
    float* Ps = smem + SM_PS;   // [q][key]   stride 212 (overlaps Qs/Ks)

    const int blk  = blockIdx.x;   // 0..63 window
    const int b    = blockIdx.y;   // 0..15
    const int head = blockIdx.z;   // 0..7
    const int by = blk >> 3, bx = blk & 7;

    const int tid = threadIdx.x;
    const int lane = tid & 31, warp = tid >> 5;
    const int g = lane >> 2, tig = lane & 3;

    // --- load Q tile (64 x 32) ---
    const float* qb = g_q + (size_t)b * HW * 256;
#pragma unroll
    for (int i = 0; i < 16; i++) {
        int idx = tid + i * 128;             // 2048 elems
        int r = idx >> 5, d = idx & 31;
        int gh = by * 8 + (r >> 3), gw = bx * 8 + (r & 7);
        Qs[r * 36 + d] = f2tf(qb[(size_t)(gh * 64 + gw) * 256 + head * 32 + d]);
    }
    // --- gather K/V window (196 rows x 64), OOB -> 0 (matches reference zero-pad) ---
    const float* kvb = g_kv + (size_t)b * HW * 512 + head * 64;
    for (int i = 0; i < 98; i++) {
        int idx = tid + i * 128;             // 12544 elems
        int widx = idx >> 6, d = idx & 63;
        int wy = widx / 14, wx = widx - wy * 14;
        int gh = by * 8 - 3 + wy, gw = bx * 8 - 3 + wx;
        float v = 0.f;
        if ((unsigned)gh < 64u && (unsigned)gw < 64u)
            v = kvb[(size_t)(gh * 64 + gw) * 512 + d];
        v = f2tf(v);
        if (d < 32) Ks[widx * 36 + d] = v;
        else        Vs[widx * 40 + (d - 32)] = v;
    }
    // zero the 4 padded key rows (196..199)
    if (tid < 128) {
        int wr2 = 196 + (tid >> 5), dd = tid & 31;
        Ks[wr2 * 36 + dd] = 0.f;
        Vs[wr2 * 40 + dd] = 0.f;
    }
    __syncthreads();

    // --- QK: each warp 16 q-rows x 200 key cols (25 n-tiles), K=32 ---
    float acc[25][4];
#pragma unroll
    for (int nt = 0; nt < 25; nt++)
#pragma unroll
        for (int j = 0; j < 4; j++) acc[nt][j] = 0.f;

    const int r0 = warp * 16 + g;
#pragma unroll
    for (int ks = 0; ks < 4; ks++) {
        const int k0 = ks * 8;
        unsigned a0 = __float_as_uint(Qs[r0 * 36 + k0 + tig]);
        unsigned a1 = __float_as_uint(Qs[(r0 + 8) * 36 + k0 + tig]);
        unsigned a2 = __float_as_uint(Qs[r0 * 36 + k0 + tig + 4]);
        unsigned a3 = __float_as_uint(Qs[(r0 + 8) * 36 + k0 + tig + 4]);
#pragma unroll
        for (int nt = 0; nt < 25; nt++) {
            unsigned b0 = __float_as_uint(Ks[(nt * 8 + g) * 36 + k0 + tig]);
            unsigned b1 = __float_as_uint(Ks[(nt * 8 + g) * 36 + k0 + tig + 4]);
            mma_tf32(acc[nt][0], acc[nt][1], acc[nt][2], acc[nt][3],
                     a0, a1, a2, a3, b0, b1);
        }
    }
    __syncthreads();   // Qs/Ks dead everywhere -> Ps region may be overwritten

    // --- softmax (rows r0 and r0+8 per thread, cols 2*tig{,+1} per n-tile) ---
    const int r1 = r0 + 8;
    const float* pbh = pb + (size_t)head * NQ * NKEY;
    float m0 = -1e30f, m1 = -1e30f;
#pragma unroll
    for (int nt = 0; nt < 25; nt++) {
        int c0 = nt * 8 + 2 * tig;
        bool v0 = c0 < 196, v1 = (c0 + 1) < 196;
        acc[nt][0] = v0 ? acc[nt][0] * ATTN_SCALE + __ldg(&pbh[r0 * 196 + c0])     : -1e30f;
        acc[nt][1] = v1 ? acc[nt][1] * ATTN_SCALE + __ldg(&pbh[r0 * 196 + c0 + 1]) : -1e30f;
        acc[nt][2] = v0 ? acc[nt][2] * ATTN_SCALE + __ldg(&pbh[r1 * 196 + c0])     : -1e30f;
        acc[nt][3] = v1 ? acc[nt][3] * ATTN_SCALE + __ldg(&pbh[r1 * 196 + c0 + 1]) : -1e30f;
        m0 = fmaxf(m0, fmaxf(acc[nt][0], acc[nt][1]));
        m1 = fmaxf(m1, fmaxf(acc[nt][2], acc[nt][3]));
    }
    m0 = fmaxf(m0, __shfl_xor_sync(0xffffffffu, m0, 1));
    m0 = fmaxf(m0, __shfl_xor_sync(0xffffffffu, m0, 2));
    m1 = fmaxf(m1, __shfl_xor_sync(0xffffffffu, m1, 1));
    m1 = fmaxf(m1, __shfl_xor_sync(0xffffffffu, m1, 2));

    float l0 = 0.f, l1 = 0.f;
#pragma unroll
    for (int nt = 0; nt < 25; nt++) {
        acc[nt][0] = __expf(acc[nt][0] - m0);
        acc[nt][1] = __expf(acc[nt][1] - m0);
        acc[nt][2] = __expf(acc[nt][2] - m1);
        acc[nt][3] = __expf(acc[nt][3] - m1);
        l0 += acc[nt][0] + acc[nt][1];
        l1 += acc[nt][2] + acc[nt][3];
    }
    l0 += __shfl_xor_sync(0xffffffffu, l0, 1);
    l0 += __shfl_xor_sync(0xffffffffu, l0, 2);
    l1 += __shfl_xor_sync(0xffffffffu, l1, 1);
    l1 += __shfl_xor_sync(0xffffffffu, l1, 2);
    const float inv0 = 1.f / l0, inv1 = 1.f / l1;

#pragma unroll
    for (int nt = 0; nt < 25; nt++) {
        int c0 = nt * 8 + 2 * tig;
        float2 p0 = make_float2(f2tf(acc[nt][0] * inv0), f2tf(acc[nt][1] * inv0));
        float2 p1 = make_float2(f2tf(acc[nt][2] * inv1), f2tf(acc[nt][3] * inv1));
        *(float2*)&Ps[r0 * 212 + c0] = p0;
        *(float2*)&Ps[r1 * 212 + c0] = p1;
    }
    __syncwarp();   // Ps rows of this warp are produced & consumed by this warp only

    // --- PV: out[16 x 32] per warp, K loop over 200 keys ---
    float o[4][4];
#pragma unroll
    for (int nt = 0; nt < 4; nt++)
#pragma unroll
        for (int j = 0; j < 4; j++) o[nt][j] = 0.f;

#pragma unroll
    for (int kk = 0; kk < 25; kk++) {
        const int k0 = kk * 8;
        unsigned a0 = __float_as_uint(Ps[r0 * 212 + k0 + tig]);
        unsigned a1 = __float_as_uint(Ps[r1 * 212 + k0 + tig]);
        unsigned a2 = __float_as_uint(Ps[r0 * 212 + k0 + tig + 4]);
        unsigned a3 = __float_as_uint(Ps[r1 * 212 + k0 + tig + 4]);
#pragma unroll
        for (int nt = 0; nt < 4; nt++) {
            unsigned b0 = __float_as_uint(Vs[(k0 + tig) * 40 + nt * 8 + g]);
            unsigned b1 = __float_as_uint(Vs[(k0 + tig + 4) * 40 + nt * 8 + g]);
            mma_tf32(o[nt][0], o[nt][1], o[nt][2], o[nt][3],
                     a0, a1, a2, a3, b0, b1);
        }
    }

    // --- epilogue: out[b][head*32+d][gh][gw] ---
    const size_t ob = ((size_t)b * 256 + head * 32);
    const int gh0 = by * 8 + (r0 >> 3), gw0 = bx * 8 + (r0 & 7);
    const int gh1 = by * 8 + (r1 >> 3), gw1 = bx * 8 + (r1 & 7);
#pragma unroll
    for (int nt = 0; nt < 4; nt++) {
        int d0 = nt * 8 + 2 * tig;
        out[(ob + d0    ) * HW + gh0 * 64 + gw0] = o[nt][0];
        out[(ob + d0 + 1) * HW + gh0 * 64 + gw0] = o[nt][1];
        out[(ob + d0    ) * HW + gh1 * 64 + gw1] = o[nt][2];
        out[(ob + d0 + 1) * HW + gh1 * 64 + gw1] = o[nt][3];
    }
}

// ---------------------------------------------------------------------------
extern "C" void kernel_launch(void* const* d_in, const int* in_sizes, int n_in,
                              void* d_out, int out_size) {
    const float* x   = (const float*)d_in[0];
    const float* Wq  = (const float*)d_in[1];
    const float* Wkv = (const float*)d_in[2];
    const float* pb  = (const float*)d_in[3];
    float* out = (float*)d_out;

    cudaFuncSetAttribute(halo_attn, cudaFuncAttributeMaxDynamicSharedMemorySize,
                         SM_FLOATS * (int)sizeof(float));

    qkv_gemm<<<dim3(12, 1024), 128>>>(x, Wq, Wkv);
    halo_attn<<<dim3(64, 16, 8), 128, SM_FLOATS * (int)sizeof(float)>>>(pb, out);
}

// round 5
// speedup vs baseline: 2.8129x; 2.8129x over previous
#include <cuda_runtime.h>

#define BATCH 16
#define CIN   256
#define IMG   64
#define HW    4096
#define NHEADS 8
#define NQ    64
#define NKEY  196
#define NROWP 208
#define ATTN_SCALE 0.17677669529663687f

// Scratch (allocation-free rule: __device__ globals). Values stored pre-rounded to tf32.
__device__ float g_q [BATCH * HW * 256];   // [b][h][w][head*32+d]
__device__ float g_kv[BATCH * HW * 512];   // [b][h][w][head*64+d]; d<32 = K, d>=32 = V

__device__ __forceinline__ float f2tf(float x) {
    unsigned r;
    asm("cvt.rna.tf32.f32 %0, %1;" : "=r"(r) : "f"(x));
    return __uint_as_float(r);
}
__device__ __forceinline__ unsigned fu(float x) { return __float_as_uint(x); }

__device__ __forceinline__ void mma_tf32(float& c0, float& c1, float& c2, float& c3,
                                         unsigned a0, unsigned a1, unsigned a2, unsigned a3,
                                         unsigned b0, unsigned b1) {
    asm volatile(
        "mma.sync.aligned.m16n8k8.row.col.f32.tf32.tf32.f32 "
        "{%0,%1,%2,%3},{%4,%5,%6,%7},{%8,%9},{%0,%1,%2,%3};\n"
        : "+f"(c0), "+f"(c1), "+f"(c2), "+f"(c3)
        : "r"(a0), "r"(a1), "r"(a2), "r"(a3), "r"(b0), "r"(b1));
}

// ---------------------------------------------------------------------------
// Kernel 1: QKV projection GEMM, 128x128 CTA tile, 256 threads (8 warps 4x2 of 32x64),
// register-staged k-pipeline. Outputs pre-rounded to tf32.
// ---------------------------------------------------------------------------
__global__ __launch_bounds__(256) void qkv_gemm(const float* __restrict__ x,
                                                const float* __restrict__ Wq,
                                                const float* __restrict__ Wkv) {
    __shared__ float As[128 * 20];   // [m][k] stride 20
    __shared__ float Bs[16 * 136];   // [k][n] stride 136

    const int nbase = blockIdx.x << 7;            // 0..5 -> 0..640
    const int bidy  = blockIdx.y;                 // 0..511
    const int b     = bidy >> 5;
    const int mbase = (bidy & 31) << 7;

    const float* xb = x + (size_t)b * CIN * HW;

    const int tid = threadIdx.x;
    const int lane = tid & 31, warp = tid >> 5;
    const int wr = warp >> 1, wc = warp & 1;
    const int g = lane >> 2, tig = lane & 3;

    float acc[2][8][4];
#pragma unroll
    for (int mt = 0; mt < 2; mt++)
#pragma unroll
        for (int nt = 0; nt < 8; nt++)
#pragma unroll
            for (int j = 0; j < 4; j++) acc[mt][nt][j] = 0.f;

    float ra[8], rb[8];

    auto loadT = [&](int kt) {
        const int kc = kt * 16;
#pragma unroll
        for (int i = 0; i < 8; i++) {
            int idx = tid + i * 256;
            int m = idx & 127, kk = idx >> 7;
            ra[i] = xb[(size_t)(kc + kk) * HW + mbase + m];
        }
#pragma unroll
        for (int i = 0; i < 8; i++) {
            int idx = tid + i * 256;
            int kk = idx & 15, n = idx >> 4;
            int ng = nbase + n;
            const float* Wp = (ng < 256) ? (Wq + (size_t)ng * CIN)
                                         : (Wkv + (size_t)(ng - 256) * CIN);
            rb[i] = Wp[kc + kk];
        }
    };
    auto storeT = [&]() {
#pragma unroll
        for (int i = 0; i < 8; i++) {
            int idx = tid + i * 256;
            As[(idx & 127) * 20 + (idx >> 7)] = f2tf(ra[i]);
        }
#pragma unroll
        for (int i = 0; i < 8; i++) {
            int idx = tid + i * 256;
            Bs[(idx & 15) * 136 + (idx >> 4)] = f2tf(rb[i]);
        }
    };

    loadT(0);
    storeT();
    __syncthreads();

    for (int kt = 0; kt < 16; kt++) {
        if (kt < 15) loadT(kt + 1);
#pragma unroll
        for (int ks = 0; ks < 2; ks++) {
            const int k0 = ks * 8;
            unsigned a[2][4];
#pragma unroll
            for (int mt = 0; mt < 2; mt++) {
                int r = wr * 32 + mt * 16 + g;
                a[mt][0] = fu(As[r * 20 + k0 + tig]);
                a[mt][1] = fu(As[(r + 8) * 20 + k0 + tig]);
                a[mt][2] = fu(As[r * 20 + k0 + tig + 4]);
                a[mt][3] = fu(As[(r + 8) * 20 + k0 + tig + 4]);
            }
#pragma unroll
            for (int nt = 0; nt < 8; nt++) {
                int cB = wc * 64 + nt * 8 + g;
                unsigned b0 = fu(Bs[(k0 + tig) * 136 + cB]);
                unsigned b1 = fu(Bs[(k0 + tig + 4) * 136 + cB]);
                mma_tf32(acc[0][nt][0], acc[0][nt][1], acc[0][nt][2], acc[0][nt][3],
                         a[0][0], a[0][1], a[0][2], a[0][3], b0, b1);
                mma_tf32(acc[1][nt][0], acc[1][nt][1], acc[1][nt][2], acc[1][nt][3],
                         a[1][0], a[1][1], a[1][2], a[1][3], b0, b1);
            }
        }
        if (kt < 15) { __syncthreads(); storeT(); __syncthreads(); }
    }

    // Epilogue: 128-col block entirely in q (nbase<256) or kv. Pre-round to tf32.
    float* dst; int stride, noff;
    if (nbase < 256) { dst = g_q;  stride = 256; noff = nbase; }
    else             { dst = g_kv; stride = 512; noff = nbase - 256; }
    const size_t rowbase = (size_t)b * HW + mbase;

#pragma unroll
    for (int mt = 0; mt < 2; mt++) {
        int r = wr * 32 + mt * 16 + g;
#pragma unroll
        for (int nt = 0; nt < 8; nt++) {
            int c = wc * 64 + nt * 8 + 2 * tig;
            float2 v0 = make_float2(f2tf(acc[mt][nt][0]), f2tf(acc[mt][nt][1]));
            float2 v1 = make_float2(f2tf(acc[mt][nt][2]), f2tf(acc[mt][nt][3]));
            *(float2*)&dst[(rowbase + r    ) * stride + noff + c] = v0;
            *(float2*)&dst[(rowbase + r + 8) * stride + noff + c] = v1;
        }
    }
}

// ---------------------------------------------------------------------------
// Kernel 2: halo attention. CTA = (window, batch, head), 256 threads / 8 warps.
// warp = qw*2 + kh : qw = 16-q-row block, kh = key half (13 tiles of 8 keys each;
// 208 padded key rows, rows 196..207 zero).
// P smem eliminated: QK accumulator fragments shuffled into PV A-fragments.
// ---------------------------------------------------------------------------
// smem float layout:
//  Vs     @ 0      : 208*40 = 8320
//  Ks     @ 8320   : 208*36 = 7488
//  Qs     @ 15808  : 64*36  = 2304   (Os overlaps: 64*34 = 2176, used after QK)
//  redM   @ 18112  : 128
//  redL   @ 18240  : 128
//  rowoff @ 18368  : 208 (ints)
#define SMF_TOTAL 18576

__global__ __launch_bounds__(256) void halo_attn(const float* __restrict__ pb,
                                                 float* __restrict__ out) {
    extern __shared__ float smem[];
    float* Vs   = smem;
    float* Ks   = smem + 8320;
    float* Qs   = smem + 15808;
    float* Os   = smem + 15808;   // overlaps Qs (Qs dead after QK sync)
    float* redM = smem + 18112;
    float* redL = smem + 18240;
    int*  rowoff = (int*)(smem + 18368);

    const int blk = blockIdx.x, b = blockIdx.y, head = blockIdx.z;
    const int by = blk >> 3, bx = blk & 7;

    const int tid = threadIdx.x;
    const int lane = tid & 31, warp = tid >> 5;
    const int qw = warp >> 1, kh = warp & 1;
    const int g = lane >> 2, tig = lane & 3;

    // --- window row offset table (once per CTA; kills div-by-14 in gather) ---
    if (tid < NROWP) {
        int wy = tid / 14, wx = tid - wy * 14;
        int gh = by * 8 - 3 + wy, gw = bx * 8 - 3 + wx;
        int off = -1;
        if (tid < NKEY && (unsigned)gh < 64u && (unsigned)gw < 64u)
            off = (gh * 64 + gw) * 512;
        rowoff[tid] = off;
    }

    // --- Q tile load (values already tf32-rounded) ---
    const float* qb = g_q + (size_t)b * HW * 256 + head * 32;
    {
        int t8 = tid & 7, r = tid >> 3;        // 8 threads/row, 32 rows/iter
#pragma unroll
        for (int i = 0; i < 2; i++) {
            int rr = r + i * 32;
            int gh = by * 8 + (rr >> 3), gw = bx * 8 + (rr & 7);
            float4 v = *(const float4*)&qb[(size_t)(gh * 64 + gw) * 256 + t8 * 4];
            *(float4*)&Qs[rr * 36 + t8 * 4] = v;
        }
    }
    __syncthreads();   // rowoff ready

    // --- K/V gather: float4, 16 rows/iter, OOB rows -> 0 ---
    const float* kvb = g_kv + (size_t)b * HW * 512 + head * 64;
    {
        int d4 = (tid & 15) * 4;
        int rb0 = tid >> 4;
#pragma unroll
        for (int i = 0; i < 13; i++) {
            int r = rb0 + i * 16;              // 0..207
            int off = rowoff[r];
            float4 v = make_float4(0.f, 0.f, 0.f, 0.f);
            if (off >= 0) v = *(const float4*)&kvb[off + d4];
            if (d4 < 32) *(float4*)&Ks[r * 36 + d4] = v;
            else         *(float4*)&Vs[r * 40 + (d4 - 32)] = v;
        }
    }
    __syncthreads();

    // --- QK: warp covers 16 q-rows x 104 keys (13 tiles), K=32 ---
    const int r0 = qw * 16 + g, r1 = r0 + 8;
    const int ntb = kh * 13;
    float acc[13][4];
#pragma unroll
    for (int t = 0; t < 13; t++)
#pragma unroll
        for (int j = 0; j < 4; j++) acc[t][j] = 0.f;

#pragma unroll
    for (int ks = 0; ks < 4; ks++) {
        const int k0 = ks * 8;
        unsigned a0 = fu(Qs[r0 * 36 + k0 + tig]);
        unsigned a1 = fu(Qs[r1 * 36 + k0 + tig]);
        unsigned a2 = fu(Qs[r0 * 36 + k0 + tig + 4]);
        unsigned a3 = fu(Qs[r1 * 36 + k0 + tig + 4]);
#pragma unroll
        for (int t = 0; t < 13; t++) {
            int row = (ntb + t) * 8 + g;
            unsigned b0 = fu(Ks[row * 36 + k0 + tig]);
            unsigned b1 = fu(Ks[row * 36 + k0 + tig + 4]);
            mma_tf32(acc[t][0], acc[t][1], acc[t][2], acc[t][3],
                     a0, a1, a2, a3, b0, b1);
        }
    }

    // --- scale + bias + local softmax (per key-half) ---
    const float* pbh = pb + (size_t)head * NQ * NKEY;
    float m0 = -1e30f, m1 = -1e30f;
#pragma unroll
    for (int t = 0; t < 13; t++) {
        int c0 = (ntb + t) * 8 + 2 * tig;
        if (c0 < NKEY) {
            float2 bz0 = *(const float2*)&pbh[r0 * NKEY + c0];
            float2 bz1 = *(const float2*)&pbh[r1 * NKEY + c0];
            acc[t][0] = acc[t][0] * ATTN_SCALE + bz0.x;
            acc[t][1] = acc[t][1] * ATTN_SCALE + bz0.y;
            acc[t][2] = acc[t][2] * ATTN_SCALE + bz1.x;
            acc[t][3] = acc[t][3] * ATTN_SCALE + bz1.y;
        } else {
            acc[t][0] = acc[t][1] = acc[t][2] = acc[t][3] = -1e30f;
        }
        m0 = fmaxf(m0, fmaxf(acc[t][0], acc[t][1]));
        m1 = fmaxf(m1, fmaxf(acc[t][2], acc[t][3]));
    }
    m0 = fmaxf(m0, __shfl_xor_sync(0xffffffffu, m0, 1));
    m0 = fmaxf(m0, __shfl_xor_sync(0xffffffffu, m0, 2));
    m1 = fmaxf(m1, __shfl_xor_sync(0xffffffffu, m1, 1));
    m1 = fmaxf(m1, __shfl_xor_sync(0xffffffffu, m1, 2));

    float l0 = 0.f, l1 = 0.f;
#pragma unroll
    for (int t = 0; t < 13; t++) {
        acc[t][0] = __expf(acc[t][0] - m0);
        acc[t][1] = __expf(acc[t][1] - m0);
        acc[t][2] = __expf(acc[t][2] - m1);
        acc[t][3] = __expf(acc[t][3] - m1);
        l0 += acc[t][0] + acc[t][1];
        l1 += acc[t][2] + acc[t][3];
    }
    l0 += __shfl_xor_sync(0xffffffffu, l0, 1);
    l0 += __shfl_xor_sync(0xffffffffu, l0, 2);
    l1 += __shfl_xor_sync(0xffffffffu, l1, 1);
    l1 += __shfl_xor_sync(0xffffffffu, l1, 2);

    // --- exchange (m, l) between the two key-half warps of this q-block ---
    if (tig == 0) {
        redM[warp * 16 + g]     = m0;
        redM[warp * 16 + g + 8] = m1;
        redL[warp * 16 + g]     = l0;
        redL[warp * 16 + g + 8] = l1;
    }
    __syncthreads();      // also: QK fully done -> Qs dead, Os region usable
    const int ow = qw * 2 + (1 - kh);
    float mo0 = redM[ow * 16 + g], mo1 = redM[ow * 16 + g + 8];
    float lo0 = redL[ow * 16 + g], lo1 = redL[ow * 16 + g + 8];
    float M0 = fmaxf(m0, mo0), M1 = fmaxf(m1, mo1);
    float e0 = __expf(m0 - M0), e1 = __expf(m1 - M1);
    float den0 = l0 * e0 + lo0 * __expf(mo0 - M0);
    float den1 = l1 * e1 + lo1 * __expf(mo1 - M1);
    float fac0 = e0 / den0, fac1 = e1 / den1;

    // --- PV: P fragments built from acc via intra-quad shuffles (no Ps smem) ---
    float o[4][4];
#pragma unroll
    for (int nt = 0; nt < 4; nt++)
#pragma unroll
        for (int j = 0; j < 4; j++) o[nt][j] = 0.f;

    const int srcA = (lane & 28) | (tig >> 1);
    const int srcB = srcA + 2;
    const bool odd = (tig & 1);
#pragma unroll
    for (int t = 0; t < 13; t++) {
        float p00 = __shfl_sync(0xffffffffu, acc[t][0], srcA);
        float p01 = __shfl_sync(0xffffffffu, acc[t][1], srcA);
        float p10 = __shfl_sync(0xffffffffu, acc[t][2], srcA);
        float p11 = __shfl_sync(0xffffffffu, acc[t][3], srcA);
        float q00 = __shfl_sync(0xffffffffu, acc[t][0], srcB);
        float q01 = __shfl_sync(0xffffffffu, acc[t][1], srcB);
        float q10 = __shfl_sync(0xffffffffu, acc[t][2], srcB);
        float q11 = __shfl_sync(0xffffffffu, acc[t][3], srcB);
        unsigned a0 = fu(f2tf(odd ? p01 : p00));   // P[r0][kb+tig]
        unsigned a1 = fu(f2tf(odd ? p11 : p10));   // P[r1][kb+tig]
        unsigned a2 = fu(f2tf(odd ? q01 : q00));   // P[r0][kb+tig+4]
        unsigned a3 = fu(f2tf(odd ? q11 : q10));   // P[r1][kb+tig+4]
        const int krow = (ntb + t) * 8;
#pragma unroll
        for (int nt = 0; nt < 4; nt++) {
            unsigned b0 = fu(Vs[(krow + tig) * 40 + nt * 8 + g]);
            unsigned b1 = fu(Vs[(krow + tig + 4) * 40 + nt * 8 + g]);
            mma_tf32(o[nt][0], o[nt][1], o[nt][2], o[nt][3],
                     a0, a1, a2, a3, b0, b1);
        }
    }
#pragma unroll
    for (int nt = 0; nt < 4; nt++) {
        o[nt][0] *= fac0; o[nt][1] *= fac0;
        o[nt][2] *= fac1; o[nt][3] *= fac1;
    }

    // --- combine key halves in Os[64][34], then coalesced store ---
    if (kh == 1) {
#pragma unroll
        for (int nt = 0; nt < 4; nt++) {
            int c = nt * 8 + 2 * tig;
            *(float2*)&Os[r0 * 34 + c] = make_float2(o[nt][0], o[nt][1]);
            *(float2*)&Os[r1 * 34 + c] = make_float2(o[nt][2], o[nt][3]);
        }
    }
    __syncthreads();
    if (kh == 0) {
#pragma unroll
        for (int nt = 0; nt < 4; nt++) {
            int c = nt * 8 + 2 * tig;
            float2 u0 = *(float2*)&Os[r0 * 34 + c];
            float2 u1 = *(float2*)&Os[r1 * 34 + c];
            u0.x += o[nt][0]; u0.y += o[nt][1];
            u1.x += o[nt][2]; u1.y += o[nt][3];
            *(float2*)&Os[r0 * 34 + c] = u0;
            *(float2*)&Os[r1 * 34 + c] = u1;
        }
    }
    __syncthreads();

    // --- final write: out[b][head*32+d][gh][gw], contiguous along gw ---
    const size_t ob = (size_t)b * 256 + head * 32;
    const int qx = tid & 7, d = tid >> 3;
#pragma unroll
    for (int qy = 0; qy < 8; qy++) {
        out[(ob + d) * HW + (size_t)(by * 8 + qy) * 64 + bx * 8 + qx] =
            Os[(qy * 8 + qx) * 34 + d];
    }
}

// ---------------------------------------------------------------------------
extern "C" void kernel_launch(void* const* d_in, const int* in_sizes, int n_in,
                              void* d_out, int out_size) {
    const float* x   = (const float*)d_in[0];
    const float* Wq  = (const float*)d_in[1];
    const float* Wkv = (const float*)d_in[2];
    const float* pb  = (const float*)d_in[3];
    float* out = (float*)d_out;

    cudaFuncSetAttribute(halo_attn, cudaFuncAttributeMaxDynamicSharedMemorySize,
                         SMF_TOTAL * (int)sizeof(float));

    qkv_gemm<<<dim3(6, 512), 256>>>(x, Wq, Wkv);
    halo_attn<<<dim3(64, 16, 8), 256, SMF_TOTAL * (int)sizeof(float)>>>(pb, out);
}

// round 6
// speedup vs baseline: 3.2099x; 1.1411x over previous
#include <cuda_runtime.h>

#define BATCH 16
#define CIN   256
#define IMG   64
#define HW    4096
#define NHEADS 8
#define NQ    64
#define NKEY  196
#define NROWP 208
#define ATTN_SCALE 0.17677669529663687f

// Scratch (allocation-free rule: __device__ globals). Values stored pre-rounded to tf32.
__device__ float g_q [BATCH * HW * 256];   // [b][h][w][head*32+d]
__device__ float g_kv[BATCH * HW * 512];   // [b][h][w][head*64+d]; d<32 = K, d>=32 = V

__device__ __forceinline__ float f2tf(float x) {
    unsigned r;
    asm("cvt.rna.tf32.f32 %0, %1;" : "=r"(r) : "f"(x));
    return __uint_as_float(r);
}
__device__ __forceinline__ unsigned fu(float x) { return __float_as_uint(x); }

__device__ __forceinline__ void mma_tf32(float& c0, float& c1, float& c2, float& c3,
                                         unsigned a0, unsigned a1, unsigned a2, unsigned a3,
                                         unsigned b0, unsigned b1) {
    asm volatile(
        "mma.sync.aligned.m16n8k8.row.col.f32.tf32.tf32.f32 "
        "{%0,%1,%2,%3},{%4,%5,%6,%7},{%8,%9},{%0,%1,%2,%3};\n"
        : "+f"(c0), "+f"(c1), "+f"(c2), "+f"(c3)
        : "r"(a0), "r"(a1), "r"(a2), "r"(a3), "r"(b0), "r"(b1));
}

// cp.async.cg 16B, L1-bypass, zero-fill when srcsz==0
__device__ __forceinline__ void cp16(unsigned dst, const void* src, int srcsz) {
    asm volatile("cp.async.cg.shared.global [%0], [%1], 16, %2;"
                 :: "r"(dst), "l"(src), "r"(srcsz));
}
__device__ __forceinline__ void cp_commit_wait_all() {
    asm volatile("cp.async.commit_group;");
    asm volatile("cp.async.wait_group 0;");
}

// ---------------------------------------------------------------------------
// Kernel 1: QKV projection GEMM, 128x128 CTA tile, 256 threads,
// DOUBLE-BUFFERED smem, single barrier per k-iter. Outputs pre-rounded tf32.
// ---------------------------------------------------------------------------
__global__ __launch_bounds__(256) void qkv_gemm(const float* __restrict__ x,
                                                const float* __restrict__ Wq,
                                                const float* __restrict__ Wkv) {
    __shared__ float As[2][128 * 20];   // [m][k] stride 20
    __shared__ float Bs[2][16 * 136];   // [k][n] stride 136

    const int nbase = blockIdx.x << 7;            // 0..5 -> 0..640
    const int bidy  = blockIdx.y;                 // 0..511
    const int b     = bidy >> 5;
    const int mbase = (bidy & 31) << 7;

    const float* xb = x + (size_t)b * CIN * HW;
    const float* Wbase = (nbase < 256) ? (Wq + (size_t)nbase * CIN)
                                       : (Wkv + (size_t)(nbase - 256) * CIN);

    const int tid = threadIdx.x;
    const int lane = tid & 31, warp = tid >> 5;
    const int wr = warp >> 1, wc = warp & 1;
    const int g = lane >> 2, tig = lane & 3;

    float acc[2][8][4];
#pragma unroll
    for (int mt = 0; mt < 2; mt++)
#pragma unroll
        for (int nt = 0; nt < 8; nt++)
#pragma unroll
            for (int j = 0; j < 4; j++) acc[mt][nt][j] = 0.f;

    float ra[8], rb[8];

    auto loadT = [&](int kt) {
        const int kc = kt * 16;
#pragma unroll
        for (int i = 0; i < 8; i++) {
            int idx = tid + i * 256;
            int m = idx & 127, kk = idx >> 7;
            ra[i] = xb[(size_t)(kc + kk) * HW + mbase + m];
        }
#pragma unroll
        for (int i = 0; i < 8; i++) {
            int idx = tid + i * 256;
            int kk = idx & 15, n = idx >> 4;
            rb[i] = Wbase[(size_t)n * CIN + kc + kk];
        }
    };
    auto storeT = [&](int buf) {
#pragma unroll
        for (int i = 0; i < 8; i++) {
            int idx = tid + i * 256;
            As[buf][(idx & 127) * 20 + (idx >> 7)] = f2tf(ra[i]);
        }
#pragma unroll
        for (int i = 0; i < 8; i++) {
            int idx = tid + i * 256;
            Bs[buf][(idx & 15) * 136 + (idx >> 4)] = f2tf(rb[i]);
        }
    };

    loadT(0);
    storeT(0);
    __syncthreads();

    for (int kt = 0; kt < 16; kt++) {
        const int cur = kt & 1;
        if (kt < 15) loadT(kt + 1);
#pragma unroll
        for (int ks = 0; ks < 2; ks++) {
            const int k0 = ks * 8;
            unsigned a[2][4];
#pragma unroll
            for (int mt = 0; mt < 2; mt++) {
                int r = wr * 32 + mt * 16 + g;
                a[mt][0] = fu(As[cur][r * 20 + k0 + tig]);
                a[mt][1] = fu(As[cur][(r + 8) * 20 + k0 + tig]);
                a[mt][2] = fu(As[cur][r * 20 + k0 + tig + 4]);
                a[mt][3] = fu(As[cur][(r + 8) * 20 + k0 + tig + 4]);
            }
#pragma unroll
            for (int nt = 0; nt < 8; nt++) {
                int cB = wc * 64 + nt * 8 + g;
                unsigned b0 = fu(Bs[cur][(k0 + tig) * 136 + cB]);
                unsigned b1 = fu(Bs[cur][(k0 + tig + 4) * 136 + cB]);
                mma_tf32(acc[0][nt][0], acc[0][nt][1], acc[0][nt][2], acc[0][nt][3],
                         a[0][0], a[0][1], a[0][2], a[0][3], b0, b1);
                mma_tf32(acc[1][nt][0], acc[1][nt][1], acc[1][nt][2], acc[1][nt][3],
                         a[1][0], a[1][1], a[1][2], a[1][3], b0, b1);
            }
        }
        if (kt < 15) storeT(cur ^ 1);   // other buffer: safe vs concurrent readers
        __syncthreads();
    }

    // Epilogue: 128-col block entirely in q (nbase<256) or kv. Pre-round to tf32.
    float* dst; int stride, noff;
    if (nbase < 256) { dst = g_q;  stride = 256; noff = nbase; }
    else             { dst = g_kv; stride = 512; noff = nbase - 256; }
    const size_t rowbase = (size_t)b * HW + mbase;

#pragma unroll
    for (int mt = 0; mt < 2; mt++) {
        int r = wr * 32 + mt * 16 + g;
#pragma unroll
        for (int nt = 0; nt < 8; nt++) {
            int c = wc * 64 + nt * 8 + 2 * tig;
            float2 v0 = make_float2(f2tf(acc[mt][nt][0]), f2tf(acc[mt][nt][1]));
            float2 v1 = make_float2(f2tf(acc[mt][nt][2]), f2tf(acc[mt][nt][3]));
            *(float2*)&dst[(rowbase + r    ) * stride + noff + c] = v0;
            *(float2*)&dst[(rowbase + r + 8) * stride + noff + c] = v1;
        }
    }
}

// ---------------------------------------------------------------------------
// Kernel 2: halo attention. CTA = (window, batch, head), 256 threads / 8 warps.
// warp = qw*2 + kh. All gathers via cp.async.cg (L1-bypass, zero-fill OOB).
// ---------------------------------------------------------------------------
// smem float layout:
//  Vs     @ 0      : 208*40 = 8320
//  Ks     @ 8320   : 208*36 = 7488
//  Qs     @ 15808  : 64*36  = 2304   (Os overlaps: 64*34, used after QK)
//  redM   @ 18112  : 128
//  redL   @ 18240  : 128
//  rowoff @ 18368  : 208 (ints)
#define SMF_TOTAL 18576

__global__ __launch_bounds__(256) void halo_attn(const float* __restrict__ pb,
                                                 float* __restrict__ out) {
    extern __shared__ float smem[];
    float* Vs   = smem;
    float* Ks   = smem + 8320;
    float* Qs   = smem + 15808;
    float* Os   = smem + 15808;   // overlaps Qs (Qs dead after QK sync)
    float* redM = smem + 18112;
    float* redL = smem + 18240;
    int*  rowoff = (int*)(smem + 18368);

    const unsigned smem_b = (unsigned)__cvta_generic_to_shared(smem);
    const unsigned vs_b = smem_b;
    const unsigned ks_b = smem_b + 8320 * 4;
    const unsigned qs_b = smem_b + 15808 * 4;

    const int blk = blockIdx.x, b = blockIdx.y, head = blockIdx.z;
    const int by = blk >> 3, bx = blk & 7;

    const int tid = threadIdx.x;
    const int lane = tid & 31, warp = tid >> 5;
    const int qw = warp >> 1, kh = warp & 1;
    const int g = lane >> 2, tig = lane & 3;

    // --- window row offset table ---
    if (tid < NROWP) {
        int wy = tid / 14, wx = tid - wy * 14;
        int gh = by * 8 - 3 + wy, gw = bx * 8 - 3 + wx;
        int off = -1;
        if (tid < NKEY && (unsigned)gh < 64u && (unsigned)gw < 64u)
            off = (gh * 64 + gw) * 512;
        rowoff[tid] = off;
    }

    // --- Q tile: cp.async 2 x 16B per thread (always in-bounds) ---
    const float* qb = g_q + (size_t)b * HW * 256 + head * 32;
    {
        int t8 = tid & 7, r = tid >> 3;
#pragma unroll
        for (int i = 0; i < 2; i++) {
            int rr = r + i * 32;
            int gh = by * 8 + (rr >> 3), gw = bx * 8 + (rr & 7);
            cp16(qs_b + (rr * 36 + t8 * 4) * 4,
                 qb + (size_t)(gh * 64 + gw) * 256 + t8 * 4, 16);
        }
    }
    __syncthreads();   // rowoff visible

    // --- K/V gather: 13 x cp.async 16B; OOB / pad rows zero-filled ---
    const float* kvb = g_kv + (size_t)b * HW * 512 + head * 64;
    {
        int d4 = (tid & 15) * 4;
        int rb0 = tid >> 4;
        unsigned dstb = (d4 < 32) ? (ks_b + d4 * 4) : (vs_b + (d4 - 32) * 4);
        int dstride = (d4 < 32) ? 36 * 4 : 40 * 4;
#pragma unroll
        for (int i = 0; i < 13; i++) {
            int r = rb0 + i * 16;              // 0..207
            int off = rowoff[r];
            const float* src = kvb + (off >= 0 ? off : 0) + d4;
            cp16(dstb + r * dstride, src, off >= 0 ? 16 : 0);
        }
    }
    cp_commit_wait_all();
    __syncthreads();

    // --- QK: warp covers 16 q-rows x 104 keys (13 tiles), K=32 ---
    const int r0 = qw * 16 + g, r1 = r0 + 8;
    const int ntb = kh * 13;
    float acc[13][4];
#pragma unroll
    for (int t = 0; t < 13; t++)
#pragma unroll
        for (int j = 0; j < 4; j++) acc[t][j] = 0.f;

#pragma unroll
    for (int ks = 0; ks < 4; ks++) {
        const int k0 = ks * 8;
        unsigned a0 = fu(Qs[r0 * 36 + k0 + tig]);
        unsigned a1 = fu(Qs[r1 * 36 + k0 + tig]);
        unsigned a2 = fu(Qs[r0 * 36 + k0 + tig + 4]);
        unsigned a3 = fu(Qs[r1 * 36 + k0 + tig + 4]);
#pragma unroll
        for (int t = 0; t < 13; t++) {
            int row = (ntb + t) * 8 + g;
            unsigned b0 = fu(Ks[row * 36 + k0 + tig]);
            unsigned b1 = fu(Ks[row * 36 + k0 + tig + 4]);
            mma_tf32(acc[t][0], acc[t][1], acc[t][2], acc[t][3],
                     a0, a1, a2, a3, b0, b1);
        }
    }

    // --- scale + bias + local softmax (per key-half) ---
    const float* pbh = pb + (size_t)head * NQ * NKEY;
    float m0 = -1e30f, m1 = -1e30f;
#pragma unroll
    for (int t = 0; t < 13; t++) {
        int c0 = (ntb + t) * 8 + 2 * tig;
        if (c0 < NKEY) {
            float2 bz0 = *(const float2*)&pbh[r0 * NKEY + c0];
            float2 bz1 = *(const float2*)&pbh[r1 * NKEY + c0];
            acc[t][0] = acc[t][0] * ATTN_SCALE + bz0.x;
            acc[t][1] = acc[t][1] * ATTN_SCALE + bz0.y;
            acc[t][2] = acc[t][2] * ATTN_SCALE + bz1.x;
            acc[t][3] = acc[t][3] * ATTN_SCALE + bz1.y;
        } else {
            acc[t][0] = acc[t][1] = acc[t][2] = acc[t][3] = -1e30f;
        }
        m0 = fmaxf(m0, fmaxf(acc[t][0], acc[t][1]));
        m1 = fmaxf(m1, fmaxf(acc[t][2], acc[t][3]));
    }
    m0 = fmaxf(m0, __shfl_xor_sync(0xffffffffu, m0, 1));
    m0 = fmaxf(m0, __shfl_xor_sync(0xffffffffu, m0, 2));
    m1 = fmaxf(m1, __shfl_xor_sync(0xffffffffu, m1, 1));
    m1 = fmaxf(m1, __shfl_xor_sync(0xffffffffu, m1, 2));

    float l0 = 0.f, l1 = 0.f;
#pragma unroll
    for (int t = 0; t < 13; t++) {
        acc[t][0] = __expf(acc[t][0] - m0);
        acc[t][1] = __expf(acc[t][1] - m0);
        acc[t][2] = __expf(acc[t][2] - m1);
        acc[t][3] = __expf(acc[t][3] - m1);
        l0 += acc[t][0] + acc[t][1];
        l1 += acc[t][2] + acc[t][3];
    }
    l0 += __shfl_xor_sync(0xffffffffu, l0, 1);
    l0 += __shfl_xor_sync(0xffffffffu, l0, 2);
    l1 += __shfl_xor_sync(0xffffffffu, l1, 1);
    l1 += __shfl_xor_sync(0xffffffffu, l1, 2);

    // --- exchange (m, l) between the two key-half warps of this q-block ---
    if (tig == 0) {
        redM[warp * 16 + g]     = m0;
        redM[warp * 16 + g + 8] = m1;
        redL[warp * 16 + g]     = l0;
        redL[warp * 16 + g + 8] = l1;
    }
    __syncthreads();      // also: QK done -> Qs dead, Os region usable
    const int ow = qw * 2 + (1 - kh);
    float mo0 = redM[ow * 16 + g], mo1 = redM[ow * 16 + g + 8];
    float lo0 = redL[ow * 16 + g], lo1 = redL[ow * 16 + g + 8];
    float M0 = fmaxf(m0, mo0), M1 = fmaxf(m1, mo1);
    float e0 = __expf(m0 - M0), e1 = __expf(m1 - M1);
    float den0 = l0 * e0 + lo0 * __expf(mo0 - M0);
    float den1 = l1 * e1 + lo1 * __expf(mo1 - M1);
    float fac0 = e0 / den0, fac1 = e1 / den1;

    // --- PV: P fragments built from acc via intra-quad shuffles ---
    float o[4][4];
#pragma unroll
    for (int nt = 0; nt < 4; nt++)
#pragma unroll
        for (int j = 0; j < 4; j++) o[nt][j] = 0.f;

    const int srcA = (lane & 28) | (tig >> 1);
    const int srcB = srcA + 2;
    const bool odd = (tig & 1);
#pragma unroll
    for (int t = 0; t < 13; t++) {
        float p00 = __shfl_sync(0xffffffffu, acc[t][0], srcA);
        float p01 = __shfl_sync(0xffffffffu, acc[t][1], srcA);
        float p10 = __shfl_sync(0xffffffffu, acc[t][2], srcA);
        float p11 = __shfl_sync(0xffffffffu, acc[t][3], srcA);
        float q00 = __shfl_sync(0xffffffffu, acc[t][0], srcB);
        float q01 = __shfl_sync(0xffffffffu, acc[t][1], srcB);
        float q10 = __shfl_sync(0xffffffffu, acc[t][2], srcB);
        float q11 = __shfl_sync(0xffffffffu, acc[t][3], srcB);
        unsigned a0 = fu(f2tf(odd ? p01 : p00));
        unsigned a1 = fu(f2tf(odd ? p11 : p10));
        unsigned a2 = fu(f2tf(odd ? q01 : q00));
        unsigned a3 = fu(f2tf(odd ? q11 : q10));
        const int krow = (ntb + t) * 8;
#pragma unroll
        for (int nt = 0; nt < 4; nt++) {
            unsigned b0 = fu(Vs[(krow + tig) * 40 + nt * 8 + g]);
            unsigned b1 = fu(Vs[(krow + tig + 4) * 40 + nt * 8 + g]);
            mma_tf32(o[nt][0], o[nt][1], o[nt][2], o[nt][3],
                     a0, a1, a2, a3, b0, b1);
        }
    }
#pragma unroll
    for (int nt = 0; nt < 4; nt++) {
        o[nt][0] *= fac0; o[nt][1] *= fac0;
        o[nt][2] *= fac1; o[nt][3] *= fac1;
    }

    // --- combine key halves in Os[64][34], then coalesced store ---
    if (kh == 1) {
#pragma unroll
        for (int nt = 0; nt < 4; nt++) {
            int c = nt * 8 + 2 * tig;
            *(float2*)&Os[r0 * 34 + c] = make_float2(o[nt][0], o[nt][1]);
            *(float2*)&Os[r1 * 34 + c] = make_float2(o[nt][2], o[nt][3]);
        }
    }
    __syncthreads();
    if (kh == 0) {
#pragma unroll
        for (int nt = 0; nt < 4; nt++) {
            int c = nt * 8 + 2 * tig;
            float2 u0 = *(float2*)&Os[r0 * 34 + c];
            float2 u1 = *(float2*)&Os[r1 * 34 + c];
            u0.x += o[nt][0]; u0.y += o[nt][1];
            u1.x += o[nt][2]; u1.y += o[nt][3];
            *(float2*)&Os[r0 * 34 + c] = u0;
            *(float2*)&Os[r1 * 34 + c] = u1;
        }
    }
    __syncthreads();

    // --- final write: out[b][head*32+d][gh][gw], contiguous along gw ---
    const size_t ob = (size_t)b * 256 + head * 32;
    const int qx = tid & 7, d = tid >> 3;
#pragma unroll
    for (int qy = 0; qy < 8; qy++) {
        out[(ob + d) * HW + (size_t)(by * 8 + qy) * 64 + bx * 8 + qx] =
            Os[(qy * 8 + qx) * 34 + d];
    }
}

// ---------------------------------------------------------------------------
extern "C" void kernel_launch(void* const* d_in, const int* in_sizes, int n_in,
                              void* d_out, int out_size) {
    const float* x   = (const float*)d_in[0];
    const float* Wq  = (const float*)d_in[1];
    const float* Wkv = (const float*)d_in[2];
    const float* pb  = (const float*)d_in[3];
    float* out = (float*)d_out;

    cudaFuncSetAttribute(halo_attn, cudaFuncAttributeMaxDynamicSharedMemorySize,
                         SMF_TOTAL * (int)sizeof(float));

    qkv_gemm<<<dim3(6, 512), 256>>>(x, Wq, Wkv);
    halo_attn<<<dim3(64, 16, 8), 256, SMF_TOTAL * (int)sizeof(float)>>>(pb, out);
}

// round 9
// speedup vs baseline: 3.9461x; 1.2294x over previous
#include <cuda_runtime.h>

#define BATCH 16
#define CIN   256
#define IMG   64
#define HW    4096
#define NHEADS 8
#define NQ    64
#define NKEY  196
#define NROWP 208
#define ATTN_SCALE 0.17677669529663687f

// Scratch (allocation-free rule: __device__ globals). Values stored pre-rounded to tf32.
__device__ float g_q [BATCH * HW * 256];   // [b][h][w][head*32+d]
__device__ float g_kv[BATCH * HW * 512];   // [b][h][w][head*64+d]; d<32 = K, d>=32 = V

__device__ __forceinline__ float f2tf(float x) {
    unsigned r;
    asm("cvt.rna.tf32.f32 %0, %1;" : "=r"(r) : "f"(x));
    return __uint_as_float(r);
}
__device__ __forceinline__ unsigned fu(float x) { return __float_as_uint(x); }

__device__ __forceinline__ void mma_tf32(float& c0, float& c1, float& c2, float& c3,
                                         unsigned a0, unsigned a1, unsigned a2, unsigned a3,
                                         unsigned b0, unsigned b1) {
    asm volatile(
        "mma.sync.aligned.m16n8k8.row.col.f32.tf32.tf32.f32 "
        "{%0,%1,%2,%3},{%4,%5,%6,%7},{%8,%9},{%0,%1,%2,%3};\n"
        : "+f"(c0), "+f"(c1), "+f"(c2), "+f"(c3)
        : "r"(a0), "r"(a1), "r"(a2), "r"(a3), "r"(b0), "r"(b1));
}

// cp.async.cg 16B, L1-bypass, zero-fill when srcsz==0
__device__ __forceinline__ void cp16(unsigned dst, const void* src, int srcsz) {
    asm volatile("cp.async.cg.shared.global [%0], [%1], 16, %2;"
                 :: "r"(dst), "l"(src), "r"(srcsz));
}
__device__ __forceinline__ void cp16u(unsigned dst, const void* src) {
    asm volatile("cp.async.cg.shared.global [%0], [%1], 16;"
                 :: "r"(dst), "l"(src));
}
__device__ __forceinline__ void cp_commit() {
    asm volatile("cp.async.commit_group;");
}
__device__ __forceinline__ void cp_commit_wait_all() {
    asm volatile("cp.async.commit_group;");
    asm volatile("cp.async.wait_group 0;");
}

// ---------------------------------------------------------------------------
// Kernel 1: QKV projection GEMM. 128x128 CTA tile, kTile=32, 256 threads,
// cp.async 3-stage pipeline, raw f32 in smem, tf32 cvt at fragment load.
// As[k][m] stride 136 (no transpose needed: x is [c][hw]);
// Bs[n][k] stride 36 (rows are 128B contiguous in W).
// ---------------------------------------------------------------------------
#define GKT   8            // 256/32 k-iterations
#define AST   136          // As row stride (floats)
#define BST   36           // Bs row stride (floats)
#define A_SZ  (32 * AST)   // 4352 floats per stage
#define B_SZ  (128 * BST)  // 4608 floats per stage
#define STG   (A_SZ + B_SZ) // 8960 floats
#define GEMM_SMEM (3 * STG * 4)   // 107520 bytes

__global__ __launch_bounds__(256, 2) void qkv_gemm(const float* __restrict__ x,
                                                   const float* __restrict__ Wq,
                                                   const float* __restrict__ Wkv) {
    extern __shared__ float gsm[];

    const int nbase = blockIdx.x << 7;            // 0..5 -> 0..640
    const int bidy  = blockIdx.y;                 // 0..511
    const int b     = bidy >> 5;
    const int mbase = (bidy & 31) << 7;

    const float* xb = x + (size_t)b * CIN * HW + mbase;
    const float* Wbase = (nbase < 256) ? (Wq + (size_t)nbase * CIN)
                                       : (Wkv + (size_t)(nbase - 256) * CIN);

    const int tid = threadIdx.x;
    const int lane = tid & 31, warp = tid >> 5;
    const int wr = warp >> 1, wc = warp & 1;
    const int g = lane >> 2, tig = lane & 3;

    const unsigned smb = (unsigned)__cvta_generic_to_shared(gsm);

    // per-thread load coordinates (fixed)
    const int a_kk = tid >> 5;          // 0..7 (then +8,+16,+24)
    const int a_m4 = (tid & 31) * 4;
    const int b_n  = tid >> 3;          // 0..31 (then +32,..)
    const int b_k4 = (tid & 7) * 4;

    auto loadStage = [&](int kt, int stage) {
        const unsigned abase = smb + (unsigned)(stage * STG) * 4u;
        const unsigned bbase = abase + A_SZ * 4u;
        const float* xs = xb + (size_t)(kt * 32) * HW;
        const float* ws = Wbase + kt * 32;
#pragma unroll
        for (int i = 0; i < 4; i++) {
            int kk = a_kk + i * 8;
            cp16u(abase + (unsigned)(kk * AST + a_m4) * 4u, xs + (size_t)kk * HW + a_m4);
        }
#pragma unroll
        for (int i = 0; i < 4; i++) {
            int n = b_n + i * 32;
            cp16u(bbase + (unsigned)(n * BST + b_k4) * 4u, ws + (size_t)n * CIN + b_k4);
        }
        cp_commit();
    };

    float acc[2][8][4];
#pragma unroll
    for (int mt = 0; mt < 2; mt++)
#pragma unroll
        for (int nt = 0; nt < 8; nt++)
#pragma unroll
            for (int j = 0; j < 4; j++) acc[mt][nt][j] = 0.f;

    loadStage(0, 0);
    loadStage(1, 1);

    for (int kt = 0; kt < GKT; kt++) {
        const int stage = kt % 3;
        asm volatile("cp.async.wait_group 1;");
        __syncthreads();
        if (kt + 2 < GKT) loadStage(kt + 2, (kt + 2) % 3);
        else cp_commit();   // keep group counting uniform

        const float* As = gsm + stage * STG;
        const float* Bs = As + A_SZ;
#pragma unroll
        for (int ks = 0; ks < 4; ks++) {
            const int k0 = ks * 8;
            unsigned a[2][4];
#pragma unroll
            for (int mt = 0; mt < 2; mt++) {
                int r = wr * 32 + mt * 16 + g;
                a[mt][0] = fu(f2tf(As[(k0 + tig) * AST + r]));
                a[mt][1] = fu(f2tf(As[(k0 + tig) * AST + r + 8]));
                a[mt][2] = fu(f2tf(As[(k0 + tig + 4) * AST + r]));
                a[mt][3] = fu(f2tf(As[(k0 + tig + 4) * AST + r + 8]));
            }
#pragma unroll
            for (int nt = 0; nt < 8; nt++) {
                int cB = wc * 64 + nt * 8 + g;
                unsigned b0 = fu(f2tf(Bs[cB * BST + k0 + tig]));
                unsigned b1 = fu(f2tf(Bs[cB * BST + k0 + tig + 4]));
                mma_tf32(acc[0][nt][0], acc[0][nt][1], acc[0][nt][2], acc[0][nt][3],
                         a[0][0], a[0][1], a[0][2], a[0][3], b0, b1);
                mma_tf32(acc[1][nt][0], acc[1][nt][1], acc[1][nt][2], acc[1][nt][3],
                         a[1][0], a[1][1], a[1][2], a[1][3], b0, b1);
            }
        }
    }

    // Epilogue: 128-col block entirely in q (nbase<256) or kv. Pre-round to tf32.
    float* dst; int stride, noff;
    if (nbase < 256) { dst = g_q;  stride = 256; noff = nbase; }
    else             { dst = g_kv; stride = 512; noff = nbase - 256; }
    const size_t rowbase = (size_t)b * HW + mbase;

#pragma unroll
    for (int mt = 0; mt < 2; mt++) {
        int r = wr * 32 + mt * 16 + g;
#pragma unroll
        for (int nt = 0; nt < 8; nt++) {
            int c = wc * 64 + nt * 8 + 2 * tig;
            float2 v0 = make_float2(f2tf(acc[mt][nt][0]), f2tf(acc[mt][nt][1]));
            float2 v1 = make_float2(f2tf(acc[mt][nt][2]), f2tf(acc[mt][nt][3]));
            *(float2*)&dst[(rowbase + r    ) * stride + noff + c] = v0;
            *(float2*)&dst[(rowbase + r + 8) * stride + noff + c] = v1;
        }
    }
}

// ---------------------------------------------------------------------------
// Kernel 2: halo attention. CTA = (window, batch, head), 256 threads / 8 warps.
// (unchanged from the 207us version)
// ---------------------------------------------------------------------------
// smem float layout:
//  Vs     @ 0      : 208*40 = 8320
//  Ks     @ 8320   : 208*36 = 7488
//  Qs     @ 15808  : 64*36  = 2304   (Os overlaps: 64*34, used after QK)
//  redM   @ 18112  : 128
//  redL   @ 18240  : 128
//  rowoff @ 18368  : 208 (ints)
#define SMF_TOTAL 18576

__global__ __launch_bounds__(256) void halo_attn(const float* __restrict__ pb,
                                                 float* __restrict__ out) {
    extern __shared__ float smem[];
    float* Vs   = smem;
    float* Ks   = smem + 8320;
    float* Qs   = smem + 15808;
    float* Os   = smem + 15808;   // overlaps Qs (Qs dead after QK sync)
    float* redM = smem + 18112;
    float* redL = smem + 18240;
    int*  rowoff = (int*)(smem + 18368);

    const unsigned smem_b = (unsigned)__cvta_generic_to_shared(smem);
    const unsigned vs_b = smem_b;
    const unsigned ks_b = smem_b + 8320 * 4;
    const unsigned qs_b = smem_b + 15808 * 4;

    const int blk = blockIdx.x, b = blockIdx.y, head = blockIdx.z;
    const int by = blk >> 3, bx = blk & 7;

    const int tid = threadIdx.x;
    const int lane = tid & 31, warp = tid >> 5;
    const int qw = warp >> 1, kh = warp & 1;
    const int g = lane >> 2, tig = lane & 3;

    // --- window row offset table ---
    if (tid < NROWP) {
        int wy = tid / 14, wx = tid - wy * 14;
        int gh = by * 8 - 3 + wy, gw = bx * 8 - 3 + wx;
        int off = -1;
        if (tid < NKEY && (unsigned)gh < 64u && (unsigned)gw < 64u)
            off = (gh * 64 + gw) * 512;
        rowoff[tid] = off;
    }

    // --- Q tile: cp.async 2 x 16B per thread (always in-bounds) ---
    const float* qb = g_q + (size_t)b * HW * 256 + head * 32;
    {
        int t8 = tid & 7, r = tid >> 3;
#pragma unroll
        for (int i = 0; i < 2; i++) {
            int rr = r + i * 32;
            int gh = by * 8 + (rr >> 3), gw = bx * 8 + (rr & 7);
            cp16(qs_b + (rr * 36 + t8 * 4) * 4,
                 qb + (size_t)(gh * 64 + gw) * 256 + t8 * 4, 16);
        }
    }
    __syncthreads();   // rowoff visible

    // --- K/V gather: 13 x cp.async 16B; OOB / pad rows zero-filled ---
    const float* kvb = g_kv + (size_t)b * HW * 512 + head * 64;
    {
        int d4 = (tid & 15) * 4;
        int rb0 = tid >> 4;
        unsigned dstb = (d4 < 32) ? (ks_b + d4 * 4) : (vs_b + (d4 - 32) * 4);
        int dstride = (d4 < 32) ? 36 * 4 : 40 * 4;
#pragma unroll
        for (int i = 0; i < 13; i++) {
            int r = rb0 + i * 16;              // 0..207
            int off = rowoff[r];
            const float* src = kvb + (off >= 0 ? off : 0) + d4;
            cp16(dstb + r * dstride, src, off >= 0 ? 16 : 0);
        }
    }
    cp_commit_wait_all();
    __syncthreads();

    // --- QK: warp covers 16 q-rows x 104 keys (13 tiles), K=32 ---
    const int r0 = qw * 16 + g, r1 = r0 + 8;
    const int ntb = kh * 13;
    float acc[13][4];
#pragma unroll
    for (int t = 0; t < 13; t++)
#pragma unroll
        for (int j = 0; j < 4; j++) acc[t][j] = 0.f;

#pragma unroll
    for (int ks = 0; ks < 4; ks++) {
        const int k0 = ks * 8;
        unsigned a0 = fu(Qs[r0 * 36 + k0 + tig]);
        unsigned a1 = fu(Qs[r1 * 36 + k0 + tig]);
        unsigned a2 = fu(Qs[r0 * 36 + k0 + tig + 4]);
        unsigned a3 = fu(Qs[r1 * 36 + k0 + tig + 4]);
#pragma unroll
        for (int t = 0; t < 13; t++) {
            int row = (ntb + t) * 8 + g;
            unsigned b0 = fu(Ks[row * 36 + k0 + tig]);
            unsigned b1 = fu(Ks[row * 36 + k0 + tig + 4]);
            mma_tf32(acc[t][0], acc[t][1], acc[t][2], acc[t][3],
                     a0, a1, a2, a3, b0, b1);
        }
    }

    // --- scale + bias + local softmax (per key-half) ---
    const float* pbh = pb + (size_t)head * NQ * NKEY;
    float m0 = -1e30f, m1 = -1e30f;
#pragma unroll
    for (int t = 0; t < 13; t++) {
        int c0 = (ntb + t) * 8 + 2 * tig;
        if (c0 < NKEY) {
            float2 bz0 = *(const float2*)&pbh[r0 * NKEY + c0];
            float2 bz1 = *(const float2*)&pbh[r1 * NKEY + c0];
            acc[t][0] = acc[t][0] * ATTN_SCALE + bz0.x;
            acc[t][1] = acc[t][1] * ATTN_SCALE + bz0.y;
            acc[t][2] = acc[t][2] * ATTN_SCALE + bz1.x;
            acc[t][3] = acc[t][3] * ATTN_SCALE + bz1.y;
        } else {
            acc[t][0] = acc[t][1] = acc[t][2] = acc[t][3] = -1e30f;
        }
        m0 = fmaxf(m0, fmaxf(acc[t][0], acc[t][1]));
        m1 = fmaxf(m1, fmaxf(acc[t][2], acc[t][3]));
    }
    m0 = fmaxf(m0, __shfl_xor_sync(0xffffffffu, m0, 1));
    m0 = fmaxf(m0, __shfl_xor_sync(0xffffffffu, m0, 2));
    m1 = fmaxf(m1, __shfl_xor_sync(0xffffffffu, m1, 1));
    m1 = fmaxf(m1, __shfl_xor_sync(0xffffffffu, m1, 2));

    float l0 = 0.f, l1 = 0.f;
#pragma unroll
    for (int t = 0; t < 13; t++) {
        acc[t][0] = __expf(acc[t][0] - m0);
        acc[t][1] = __expf(acc[t][1] - m0);
        acc[t][2] = __expf(acc[t][2] - m1);
        acc[t][3] = __expf(acc[t][3] - m1);
        l0 += acc[t][0] + acc[t][1];
        l1 += acc[t][2] + acc[t][3];
    }
    l0 += __shfl_xor_sync(0xffffffffu, l0, 1);
    l0 += __shfl_xor_sync(0xffffffffu, l0, 2);
    l1 += __shfl_xor_sync(0xffffffffu, l1, 1);
    l1 += __shfl_xor_sync(0xffffffffu, l1, 2);

    // --- exchange (m, l) between the two key-half warps of this q-block ---
    if (tig == 0) {
        redM[warp * 16 + g]     = m0;
        redM[warp * 16 + g + 8] = m1;
        redL[warp * 16 + g]     = l0;
        redL[warp * 16 + g + 8] = l1;
    }
    __syncthreads();      // also: QK done -> Qs dead, Os region usable
    const int ow = qw * 2 + (1 - kh);
    float mo0 = redM[ow * 16 + g], mo1 = redM[ow * 16 + g + 8];
    float lo0 = redL[ow * 16 + g], lo1 = redL[ow * 16 + g + 8];
    float M0 = fmaxf(m0, mo0), M1 = fmaxf(m1, mo1);
    float e0 = __expf(m0 - M0), e1 = __expf(m1 - M1);
    float den0 = l0 * e0 + lo0 * __expf(mo0 - M0);
    float den1 = l1 * e1 + lo1 * __expf(mo1 - M1);
    float fac0 = e0 / den0, fac1 = e1 / den1;

    // --- PV: P fragments built from acc via intra-quad shuffles ---
    float o[4][4];
#pragma unroll
    for (int nt = 0; nt < 4; nt++)
#pragma unroll
        for (int j = 0; j < 4; j++) o[nt][j] = 0.f;

    const int srcA = (lane & 28) | (tig >> 1);
    const int srcB = srcA + 2;
    const bool odd = (tig & 1);
#pragma unroll
    for (int t = 0; t < 13; t++) {
        float p00 = __shfl_sync(0xffffffffu, acc[t][0], srcA);
        float p01 = __shfl_sync(0xffffffffu, acc[t][1], srcA);
        float p10 = __shfl_sync(0xffffffffu, acc[t][2], srcA);
        float p11 = __shfl_sync(0xffffffffu, acc[t][3], srcA);
        float q00 = __shfl_sync(0xffffffffu, acc[t][0], srcB);
        float q01 = __shfl_sync(0xffffffffu, acc[t][1], srcB);
        float q10 = __shfl_sync(0xffffffffu, acc[t][2], srcB);
        float q11 = __shfl_sync(0xffffffffu, acc[t][3], srcB);
        unsigned a0 = fu(f2tf(odd ? p01 : p00));
        unsigned a1 = fu(f2tf(odd ? p11 : p10));
        unsigned a2 = fu(f2tf(odd ? q01 : q00));
        unsigned a3 = fu(f2tf(odd ? q11 : q10));
        const int krow = (ntb + t) * 8;
#pragma unroll
        for (int nt = 0; nt < 4; nt++) {
            unsigned b0 = fu(Vs[(krow + tig) * 40 + nt * 8 + g]);
            unsigned b1 = fu(Vs[(krow + tig + 4) * 40 + nt * 8 + g]);
            mma_tf32(o[nt][0], o[nt][1], o[nt][2], o[nt][3],
                     a0, a1, a2, a3, b0, b1);
        }
    }
#pragma unroll
    for (int nt = 0; nt < 4; nt++) {
        o[nt][0] *= fac0; o[nt][1] *= fac0;
        o[nt][2] *= fac1; o[nt][3] *= fac1;
    }

    // --- combine key halves in Os[64][34], then coalesced store ---
    if (kh == 1) {
#pragma unroll
        for (int nt = 0; nt < 4; nt++) {
            int c = nt * 8 + 2 * tig;
            *(float2*)&Os[r0 * 34 + c] = make_float2(o[nt][0], o[nt][1]);
            *(float2*)&Os[r1 * 34 + c] = make_float2(o[nt][2], o[nt][3]);
        }
    }
    __syncthreads();
    if (kh == 0) {
#pragma unroll
        for (int nt = 0; nt < 4; nt++) {
            int c = nt * 8 + 2 * tig;
            float2 u0 = *(float2*)&Os[r0 * 34 + c];
            float2 u1 = *(float2*)&Os[r1 * 34 + c];
            u0.x += o[nt][0]; u0.y += o[nt][1];
            u1.x += o[nt][2]; u1.y += o[nt][3];
            *(float2*)&Os[r0 * 34 + c] = u0;
            *(float2*)&Os[r1 * 34 + c] = u1;
        }
    }
    __syncthreads();

    // --- final write: out[b][head*32+d][gh][gw], contiguous along gw ---
    const size_t ob = (size_t)b * 256 + head * 32;
    const int qx = tid & 7, d = tid >> 3;
#pragma unroll
    for (int qy = 0; qy < 8; qy++) {
        out[(ob + d) * HW + (size_t)(by * 8 + qy) * 64 + bx * 8 + qx] =
            Os[(qy * 8 + qx) * 34 + d];
    }
}

// ---------------------------------------------------------------------------
extern "C" void kernel_launch(void* const* d_in, const int* in_sizes, int n_in,
                              void* d_out, int out_size) {
    const float* x   = (const float*)d_in[0];
    const float* Wq  = (const float*)d_in[1];
    const float* Wkv = (const float*)d_in[2];
    const float* pb  = (const float*)d_in[3];
    float* out = (float*)d_out;

    cudaFuncSetAttribute(qkv_gemm, cudaFuncAttributeMaxDynamicSharedMemorySize,
                         GEMM_SMEM);
    cudaFuncSetAttribute(halo_attn, cudaFuncAttributeMaxDynamicSharedMemorySize,
                         SMF_TOTAL * (int)sizeof(float));

    qkv_gemm<<<dim3(6, 512), 256, GEMM_SMEM>>>(x, Wq, Wkv);
    halo_attn<<<dim3(64, 16, 8), 256, SMF_TOTAL * (int)sizeof(float)>>>(pb, out);
}